// round 8
// baseline (speedup 1.0000x reference)
#include <cuda_runtime.h>
#include <cstdint>
#include <math.h>

#define NN 100000

// ---------------- scratch ----------------
__device__ float g_X [(size_t)NN * 128];      // tf32-rounded x
__device__ float g_Q [(size_t)NN * 128];
__device__ float g_E [(size_t)NN * 20];
__device__ float g_H [(size_t)NN * 128];      // exact H (residual for FFN2)
__device__ float g_Ht[(size_t)NN * 128];      // tf32-rounded H
__device__ float g_F [(size_t)NN * 512];
__device__ float g_WT[311296];                // transposed+rounded weights [c][k]
__device__ float g_denom[20];

__device__ __forceinline__ uint32_t f2tf(float f) {
    uint32_t u; asm("cvt.rna.tf32.f32 %0, %1;" : "=r"(u) : "f"(f)); return u;
}
__device__ __forceinline__ float f2tff(float f) { return __uint_as_float(f2tf(f)); }
__device__ __forceinline__ uint32_t smem_u32(const void* p) {
    uint32_t a;
    asm("{ .reg .u64 t; cvta.to.shared.u64 t, %1; cvt.u32.u64 %0, t; }" : "=r"(a) : "l"(p));
    return a;
}
__device__ __forceinline__ void cpa16(uint32_t dst, const void* src) {
    asm volatile("cp.async.ca.shared.global [%0], [%1], 16;" :: "r"(dst), "l"(src));
}

__global__ void zero_denoms_kernel() {
    if (threadIdx.x < 20) g_denom[threadIdx.x] = 0.0f;
}

__global__ void round_x_kernel(const float* __restrict__ x) {
    size_t i = ((size_t)blockIdx.x * 256 + threadIdx.x) * 4;
    if (i >= (size_t)NN * 128) return;
    float4 v = *(const float4*)(x + i);
    v.x = f2tff(v.x); v.y = f2tff(v.y); v.z = f2tff(v.z); v.w = f2tff(v.w);
    *(float4*)(g_X + i) = v;
}

__global__ void transpose_w(const float* __restrict__ in, float* __restrict__ out,
                            int HS, int KS, int inBz, int Kb, int Ctot) {
    int z = blockIdx.z;
    int idx = blockIdx.x * 256 + threadIdx.x;
    if (idx >= Ctot * Kb) return;
    int c = idx / Kb, k = idx - c * Kb;
    out[(size_t)z * Ctot * Kb + idx] =
        f2tff(in[(size_t)z * inBz + (size_t)(c >> 5) * HS + (size_t)k * KS + (c & 31)]);
}

#define LDM_X4(r0,r1,r2,r3,addr) \
    asm volatile("ldmatrix.sync.aligned.m8n8.x4.shared.b16 {%0,%1,%2,%3}, [%4];" \
                 : "=r"(r0), "=r"(r1), "=r"(r2), "=r"(r3) : "r"(addr))
#define MMA_TF32(dd,aa,bb) \
    asm volatile("mma.sync.aligned.m16n8k8.row.col.f32.tf32.tf32.f32 " \
                 "{%0,%1,%2,%3}, {%4,%5,%6,%7}, {%8,%9}, {%0,%1,%2,%3};" \
                 : "+f"((dd)[0]), "+f"((dd)[1]), "+f"((dd)[2]), "+f"((dd)[3]) \
                 : "r"((aa)[0]), "r"((aa)[1]), "r"((aa)[2]), "r"((aa)[3]), \
                   "r"((bb)[0]), "r"((bb)[1]))

// ---------------- generic tf32 GEMM (Q / FFN1 / FFN2) ----------------
__global__ __launch_bounds__(256, 2)
void tgemm(const float* __restrict__ A, int Astride,
           const float* __restrict__ BT, int Kb,
           int kchunks,
           float* __restrict__ C, int Cstride,
           int epi,
           const float* __restrict__ bias,
           const float* __restrict__ resid,
           const float* __restrict__ gamma,
           const float* __restrict__ beta)
{
    extern __shared__ uint32_t sm[];
    char* smc = (char*)sm;
    const uint32_t sbase = smem_u32(smc);

    const int tid  = threadIdx.x;
    const int wid  = tid >> 5;
    const int lane = tid & 31;
    const int cg0  = blockIdx.y * 128;
    const int m0   = blockIdx.x * 128;
    const int m0w  = (wid >> 1) * 32;
    const int n0w  = (wid & 1) * 64;

    const int srow = tid >> 3, schk = tid & 7;
    const int lrow = lane & 7;
    const int a_hi = (lane >> 3) >> 1, a_roff = ((lane >> 3) & 1) * 8;
    const int b_hi = (lane >> 3) & 1,  b_coff = (lane >> 4) * 8;

    float d[2][8][4];
#pragma unroll
    for (int i = 0; i < 2; i++)
#pragma unroll
        for (int j = 0; j < 8; j++)
#pragma unroll
            for (int q = 0; q < 4; q++) d[i][j][q] = 0.0f;

    auto stage = [&](int bsel, int kc) {
        const int kg0 = kc * 32;
        uint32_t abase = sbase + (uint32_t)bsel * 16384u;
        uint32_t bbase = sbase + 32768u + (uint32_t)bsel * 16384u;
#pragma unroll
        for (int p = 0; p < 4; ++p) {
            int row = srow + p * 32;
            int ar  = m0 + row; if (ar >= NN) ar = NN - 1;
            uint32_t off = (uint32_t)row * 128u + (uint32_t)((schk ^ (row & 7)) << 4);
            cpa16(abase + off, A + (size_t)ar * Astride + kg0 + schk * 4);
            cpa16(bbase + off, BT + (size_t)(cg0 + row) * Kb + kg0 + schk * 4);
        }
        asm volatile("cp.async.commit_group;" ::: "memory");
    };

    stage(0, 0);
    for (int kc = 0; kc < kchunks; ++kc) {
        const int bsel = kc & 1;
        if (kc + 1 < kchunks) { stage(bsel ^ 1, kc + 1);
            asm volatile("cp.async.wait_group 1;" ::: "memory");
        } else { asm volatile("cp.async.wait_group 0;" ::: "memory"); }
        __syncthreads();
        const uint32_t abase = sbase + (uint32_t)bsel * 16384u;
        const uint32_t bbase = sbase + 32768u + (uint32_t)bsel * 16384u;
#pragma unroll
        for (int ks = 0; ks < 4; ++ks) {
            uint32_t a[2][4], b[8][2];
#pragma unroll
            for (int mf = 0; mf < 2; ++mf) {
                int r = m0w + mf * 16 + lrow + a_roff;
                uint32_t addr = abase + (uint32_t)r * 128u
                              + (uint32_t)(((2 * ks + a_hi) ^ lrow) << 4);
                LDM_X4(a[mf][0], a[mf][1], a[mf][2], a[mf][3], addr);
            }
#pragma unroll
            for (int pr = 0; pr < 4; ++pr) {
                int c = n0w + pr * 16 + lrow + b_coff;
                uint32_t addr = bbase + (uint32_t)c * 128u
                              + (uint32_t)(((2 * ks + b_hi) ^ (c & 7)) << 4);
                LDM_X4(b[2*pr][0], b[2*pr][1], b[2*pr+1][0], b[2*pr+1][1], addr);
            }
#pragma unroll
            for (int mf = 0; mf < 2; ++mf)
#pragma unroll
                for (int nf = 0; nf < 8; ++nf) MMA_TF32(d[mf][nf], a[mf], b[nf]);
        }
        __syncthreads();
    }

    float* sC = (float*)sm;
    const int g4 = lane >> 2, t4 = lane & 3;
#pragma unroll
    for (int mf = 0; mf < 2; ++mf)
#pragma unroll
        for (int nf = 0; nf < 8; ++nf) {
            int row = m0w + mf * 16 + g4;
            int col = n0w + nf * 8 + t4 * 2;
            *(float2*)(sC + row * 132 + col)       = make_float2(d[mf][nf][0], d[mf][nf][1]);
            *(float2*)(sC + (row + 8) * 132 + col) = make_float2(d[mf][nf][2], d[mf][nf][3]);
        }
    __syncthreads();

    if (epi == 2) {
        for (int rr = wid; rr < 128; rr += 8) {
            int gr = m0 + rr;
            if (gr >= NN) continue;
            const float* rp = resid + (size_t)gr * 128;
            float v0 = sC[rr * 132 + lane]      + bias[lane]      + rp[lane];
            float v1 = sC[rr * 132 + 32 + lane] + bias[32 + lane] + rp[32 + lane];
            float v2 = sC[rr * 132 + 64 + lane] + bias[64 + lane] + rp[64 + lane];
            float v3 = sC[rr * 132 + 96 + lane] + bias[96 + lane] + rp[96 + lane];
            float s1 = v0 + v1 + v2 + v3;
            float s2 = v0 * v0 + v1 * v1 + v2 * v2 + v3 * v3;
#pragma unroll
            for (int o = 16; o > 0; o >>= 1) {
                s1 += __shfl_xor_sync(0xffffffffu, s1, o);
                s2 += __shfl_xor_sync(0xffffffffu, s2, o);
            }
            float mu  = s1 * (1.0f / 128.0f);
            float var = s2 * (1.0f / 128.0f) - mu * mu;
            float rs  = rsqrtf(var + 1e-5f);
            float* dst = C + (size_t)gr * 128;
            dst[lane]      = (v0 - mu) * rs * gamma[lane]      + beta[lane];
            dst[lane + 32] = (v1 - mu) * rs * gamma[lane + 32] + beta[lane + 32];
            dst[lane + 64] = (v2 - mu) * rs * gamma[lane + 64] + beta[lane + 64];
            dst[lane + 96] = (v3 - mu) * rs * gamma[lane + 96] + beta[lane + 96];
        }
    } else {
#pragma unroll
        for (int p = 0; p < 4; ++p) {
            int i   = tid + p * 256;
            int row = i >> 3;
            int q   = (i & 7) << 4;
            int gr  = m0 + row;
            if (gr >= NN) continue;
#pragma unroll
            for (int h = 0; h < 4; ++h) {
                int c  = q + h * 4;
                float4 v = *(const float4*)(sC + row * 132 + c);
                int cg = cg0 + c;
                if (epi == 1) {
                    v.x = f2tff(fmaxf(v.x + bias[cg + 0], 0.f));
                    v.y = f2tff(fmaxf(v.y + bias[cg + 1], 0.f));
                    v.z = f2tff(fmaxf(v.z + bias[cg + 2], 0.f));
                    v.w = f2tff(fmaxf(v.w + bias[cg + 3], 0.f));
                }
                *(float4*)(C + (size_t)gr * Cstride + cg) = v;
            }
        }
    }
}

// ---------------- K GEMM with fused logits (z = r) ----------------
__global__ __launch_bounds__(256, 2)
void kgemm(const int* __restrict__ nbr, const float* __restrict__ BT)
{
    extern __shared__ uint32_t sm[];
    char* smc = (char*)sm;
    const uint32_t sbase = smem_u32(smc);
    __shared__ int rowg[128];
    __shared__ float sden[20];

    const int tid  = threadIdx.x;
    const int wid  = tid >> 5;
    const int lane = tid & 31;
    const int z    = blockIdx.z;
    const int m0   = blockIdx.x * 128;

    if (tid < 128) {
        int gr  = m0 + tid;
        int idx = (gr < NN) ? gr : (NN - 1);
        if (z > 0 && gr < NN) idx = nbr[gr * 4 + (z - 1)];
        rowg[tid] = idx;
    }
    if (tid < 20) sden[tid] = 0.0f;
    __syncthreads();

    const float* Bz = BT + (size_t)z * 16384;
    const int srow = tid >> 3, schk = tid & 7;
    const int lrow = lane & 7;
    const int a_hi = (lane >> 3) >> 1, a_roff = ((lane >> 3) & 1) * 8;
    const int b_hi = (lane >> 3) & 1,  b_coff = (lane >> 4) * 8;
    const int m0w  = (wid >> 1) * 32;
    const int n0w  = (wid & 1) * 64;

    float d[2][8][4];
#pragma unroll
    for (int i = 0; i < 2; i++)
#pragma unroll
        for (int j = 0; j < 8; j++)
#pragma unroll
            for (int q = 0; q < 4; q++) d[i][j][q] = 0.0f;

    auto stage = [&](int bsel, int kc) {
        const int kg0 = kc * 32;
        uint32_t abase = sbase + (uint32_t)bsel * 16384u;
        uint32_t bbase = sbase + 32768u + (uint32_t)bsel * 16384u;
#pragma unroll
        for (int p = 0; p < 4; ++p) {
            int row = srow + p * 32;
            uint32_t off = (uint32_t)row * 128u + (uint32_t)((schk ^ (row & 7)) << 4);
            cpa16(abase + off, g_X + (size_t)rowg[row] * 128 + kg0 + schk * 4);
            cpa16(bbase + off, Bz + (size_t)row * 128 + kg0 + schk * 4);
        }
        asm volatile("cp.async.commit_group;" ::: "memory");
    };

    stage(0, 0);
    for (int kc = 0; kc < 4; ++kc) {
        const int bsel = kc & 1;
        if (kc + 1 < 4) { stage(bsel ^ 1, kc + 1);
            asm volatile("cp.async.wait_group 1;" ::: "memory");
        } else { asm volatile("cp.async.wait_group 0;" ::: "memory"); }
        __syncthreads();
        const uint32_t abase = sbase + (uint32_t)bsel * 16384u;
        const uint32_t bbase = sbase + 32768u + (uint32_t)bsel * 16384u;
#pragma unroll
        for (int ks = 0; ks < 4; ++ks) {
            uint32_t a[2][4], b[8][2];
#pragma unroll
            for (int mf = 0; mf < 2; ++mf) {
                int r = m0w + mf * 16 + lrow + a_roff;
                uint32_t addr = abase + (uint32_t)r * 128u
                              + (uint32_t)(((2 * ks + a_hi) ^ lrow) << 4);
                LDM_X4(a[mf][0], a[mf][1], a[mf][2], a[mf][3], addr);
            }
#pragma unroll
            for (int pr = 0; pr < 4; ++pr) {
                int c = n0w + pr * 16 + lrow + b_coff;
                uint32_t addr = bbase + (uint32_t)c * 128u
                              + (uint32_t)(((2 * ks + b_hi) ^ (c & 7)) << 4);
                LDM_X4(b[2*pr][0], b[2*pr][1], b[2*pr+1][0], b[2*pr+1][1], addr);
            }
#pragma unroll
            for (int mf = 0; mf < 2; ++mf)
#pragma unroll
                for (int nf = 0; nf < 8; ++nf) MMA_TF32(d[mf][nf], a[mf], b[nf]);
        }
        __syncthreads();
    }

    float* sC = (float*)sm;
    const int g4 = lane >> 2, t4 = lane & 3;
#pragma unroll
    for (int mf = 0; mf < 2; ++mf)
#pragma unroll
        for (int nf = 0; nf < 8; ++nf) {
            int row = m0w + mf * 16 + g4;
            int col = n0w + nf * 8 + t4 * 2;
            *(float2*)(sC + row * 132 + col)       = make_float2(d[mf][nf][0], d[mf][nf][1]);
            *(float2*)(sC + (row + 8) * 132 + col) = make_float2(d[mf][nf][2], d[mf][nf][3]);
        }
    __syncthreads();

    const float scale = 0.1767766952966369f;
    float esum[4] = {0.f, 0.f, 0.f, 0.f};
    for (int rr = wid; rr < 128; rr += 8) {
        int gr = m0 + rr;
        if (gr >= NN) continue;
#pragma unroll
        for (int h = 0; h < 4; ++h) {
            float s = sC[rr * 132 + h * 32 + lane] * g_Q[(size_t)gr * 128 + h * 32 + lane];
#pragma unroll
            for (int o = 16; o > 0; o >>= 1) s += __shfl_xor_sync(0xffffffffu, s, o);
            if (lane == 0) {
                float e = expf(s * scale);
                g_E[(size_t)gr * 20 + h * 5 + z] = e;
                esum[h] += e;
            }
        }
    }
    if (lane == 0) {
#pragma unroll
        for (int h = 0; h < 4; ++h) atomicAdd(&sden[h * 5 + z], esum[h]);
    }
    __syncthreads();
    if (tid < 20 && sden[tid] != 0.0f) atomicAdd(&g_denom[tid], sden[tid]);
}

// ---------------- V GEMM x5 + combine + residual + LN1 ----------------
__global__ __launch_bounds__(256, 1)
void vcomb(const int* __restrict__ nbr, const float* __restrict__ BT,
           const float* __restrict__ x,
           const float* __restrict__ g1, const float* __restrict__ be1)
{
    extern __shared__ uint32_t sm[];
    char* smc = (char*)sm;
    const uint32_t sbase = smem_u32(smc);
    float* sZ = (float*)(smc + 65536);      // [128][132]
    __shared__ int rowg[128];
    __shared__ float sp[128 * 20];
    __shared__ float sinv[20];

    const int tid  = threadIdx.x;
    const int wid  = tid >> 5;
    const int lane = tid & 31;
    const int m0   = blockIdx.x * 128;

    if (tid < 20) sinv[tid] = 1.0f / g_denom[tid];
    for (int i = tid; i < 128 * 132; i += 256) sZ[i] = 0.0f;
    __syncthreads();
    for (int i = tid; i < 2560; i += 256) {
        int rr = i / 20, j = i - rr * 20;
        int gr = m0 + rr; if (gr >= NN) gr = NN - 1;
        sp[i] = g_E[(size_t)gr * 20 + j] * sinv[j];
    }

    const int srow = tid >> 3, schk = tid & 7;
    const int lrow = lane & 7;
    const int a_hi = (lane >> 3) >> 1, a_roff = ((lane >> 3) & 1) * 8;
    const int b_hi = (lane >> 3) & 1,  b_coff = (lane >> 4) * 8;
    const int m0w  = (wid >> 1) * 32;
    const int n0w  = (wid & 1) * 64;
    const int g4 = lane >> 2, t4 = lane & 3;

    float d[2][8][4];
#pragma unroll
    for (int i = 0; i < 2; i++)
#pragma unroll
        for (int j = 0; j < 8; j++)
#pragma unroll
            for (int q = 0; q < 4; q++) d[i][j][q] = 0.0f;

    for (int r = 0; r < 5; ++r) {
        __syncthreads();
        if (tid < 128) {
            int gr  = m0 + tid;
            int idx = (gr < NN) ? gr : (NN - 1);
            if (r > 0 && gr < NN) idx = nbr[gr * 4 + (r - 1)];
            rowg[tid] = idx;
        }
        __syncthreads();
        const float* Bz = BT + (size_t)r * 16384;

        auto stage = [&](int bsel, int kc) {
            const int kg0 = kc * 32;
            uint32_t abase = sbase + (uint32_t)bsel * 16384u;
            uint32_t bbase = sbase + 32768u + (uint32_t)bsel * 16384u;
#pragma unroll
            for (int p = 0; p < 4; ++p) {
                int row = srow + p * 32;
                uint32_t off = (uint32_t)row * 128u + (uint32_t)((schk ^ (row & 7)) << 4);
                cpa16(abase + off, g_X + (size_t)rowg[row] * 128 + kg0 + schk * 4);
                cpa16(bbase + off, Bz + (size_t)row * 128 + kg0 + schk * 4);
            }
            asm volatile("cp.async.commit_group;" ::: "memory");
        };

        stage(0, 0);
        for (int kc = 0; kc < 4; ++kc) {
            const int bsel = kc & 1;
            if (kc + 1 < 4) { stage(bsel ^ 1, kc + 1);
                asm volatile("cp.async.wait_group 1;" ::: "memory");
            } else { asm volatile("cp.async.wait_group 0;" ::: "memory"); }
            __syncthreads();
            const uint32_t abase = sbase + (uint32_t)bsel * 16384u;
            const uint32_t bbase = sbase + 32768u + (uint32_t)bsel * 16384u;
#pragma unroll
            for (int ks = 0; ks < 4; ++ks) {
                uint32_t a[2][4], b[8][2];
#pragma unroll
                for (int mf = 0; mf < 2; ++mf) {
                    int rr2 = m0w + mf * 16 + lrow + a_roff;
                    uint32_t addr = abase + (uint32_t)rr2 * 128u
                                  + (uint32_t)(((2 * ks + a_hi) ^ lrow) << 4);
                    LDM_X4(a[mf][0], a[mf][1], a[mf][2], a[mf][3], addr);
                }
#pragma unroll
                for (int pr = 0; pr < 4; ++pr) {
                    int c = n0w + pr * 16 + lrow + b_coff;
                    uint32_t addr = bbase + (uint32_t)c * 128u
                                  + (uint32_t)(((2 * ks + b_hi) ^ (c & 7)) << 4);
                    LDM_X4(b[2*pr][0], b[2*pr][1], b[2*pr+1][0], b[2*pr+1][1], addr);
                }
#pragma unroll
                for (int mf = 0; mf < 2; ++mf)
#pragma unroll
                    for (int nf = 0; nf < 8; ++nf) MMA_TF32(d[mf][nf], a[mf], b[nf]);
            }
            __syncthreads();
        }

#pragma unroll
        for (int mf = 0; mf < 2; ++mf) {
            int row0 = m0w + mf * 16 + g4;
#pragma unroll
            for (int nf = 0; nf < 8; ++nf) {
                int colb = n0w + nf * 8;
                int col  = colb + t4 * 2;
                int h    = colb >> 5;
                float p0 = sp[row0 * 20 + h * 5 + r];
                float p1 = sp[(row0 + 8) * 20 + h * 5 + r];
                float* z0 = sZ + row0 * 132 + col;
                z0[0] = fmaf(p0, d[mf][nf][0], z0[0]);
                z0[1] = fmaf(p0, d[mf][nf][1], z0[1]);
                float* z1 = sZ + (row0 + 8) * 132 + col;
                z1[0] = fmaf(p1, d[mf][nf][2], z1[0]);
                z1[1] = fmaf(p1, d[mf][nf][3], z1[1]);
                d[mf][nf][0] = d[mf][nf][1] = d[mf][nf][2] = d[mf][nf][3] = 0.f;
            }
        }
    }
    __syncthreads();

    for (int rr = wid; rr < 128; rr += 8) {
        int gr = m0 + rr;
        if (gr >= NN) continue;
        const float* xp = x + (size_t)gr * 128;
        float v0 = sZ[rr * 132 + lane]      + xp[lane];
        float v1 = sZ[rr * 132 + 32 + lane] + xp[32 + lane];
        float v2 = sZ[rr * 132 + 64 + lane] + xp[64 + lane];
        float v3 = sZ[rr * 132 + 96 + lane] + xp[96 + lane];
        float s1 = v0 + v1 + v2 + v3;
        float s2 = v0 * v0 + v1 * v1 + v2 * v2 + v3 * v3;
#pragma unroll
        for (int o = 16; o > 0; o >>= 1) {
            s1 += __shfl_xor_sync(0xffffffffu, s1, o);
            s2 += __shfl_xor_sync(0xffffffffu, s2, o);
        }
        float mu  = s1 * (1.0f / 128.0f);
        float var = s2 * (1.0f / 128.0f) - mu * mu;
        float rs  = rsqrtf(var + 1e-5f);
        float h0 = (v0 - mu) * rs * g1[lane]      + be1[lane];
        float h1 = (v1 - mu) * rs * g1[32 + lane] + be1[32 + lane];
        float h2 = (v2 - mu) * rs * g1[64 + lane] + be1[64 + lane];
        float h3 = (v3 - mu) * rs * g1[96 + lane] + be1[96 + lane];
        float* dst  = g_H  + (size_t)gr * 128;
        float* dstt = g_Ht + (size_t)gr * 128;
        dst[lane] = h0;  dst[lane + 32] = h1;  dst[lane + 64] = h2;  dst[lane + 96] = h3;
        dstt[lane] = f2tff(h0); dstt[lane + 32] = f2tff(h1);
        dstt[lane + 64] = f2tff(h2); dstt[lane + 96] = f2tff(h3);
    }
}

// ---------------- launch ----------------
extern "C" void kernel_launch(void* const* d_in, const int* in_sizes, int n_in,
                              void* d_out, int out_size)
{
    const float* x   = (const float*)d_in[0];
    const int*   nbr = (const int*)  d_in[1];
    const float* wq  = (const float*)d_in[2];
    const float* wk  = (const float*)d_in[3];
    const float* wv  = (const float*)d_in[4];
    const float* W1  = (const float*)d_in[5];
    const float* b1  = (const float*)d_in[6];
    const float* W2  = (const float*)d_in[7];
    const float* b2  = (const float*)d_in[8];
    const float* g1  = (const float*)d_in[9];
    const float* be1 = (const float*)d_in[10];
    const float* g2  = (const float*)d_in[11];
    const float* be2 = (const float*)d_in[12];
    float* out = (float*)d_out;

    void *pX, *pQ, *pH, *pHt, *pF, *pW;
    cudaGetSymbolAddress(&pX, g_X);
    cudaGetSymbolAddress(&pQ, g_Q);
    cudaGetSymbolAddress(&pH, g_H);
    cudaGetSymbolAddress(&pHt, g_Ht);
    cudaGetSymbolAddress(&pF, g_F);
    cudaGetSymbolAddress(&pW, g_WT);
    float* WT = (float*)pW;

    const size_t SMEMSZ = (size_t)128 * 132 * sizeof(float);            // 67584
    const size_t SMEMVC = 65536 + (size_t)128 * 132 * sizeof(float);    // 133120
    cudaFuncSetAttribute((const void*)tgemm,
                         cudaFuncAttributeMaxDynamicSharedMemorySize, (int)SMEMSZ);
    cudaFuncSetAttribute((const void*)kgemm,
                         cudaFuncAttributeMaxDynamicSharedMemorySize, (int)SMEMSZ);
    cudaFuncSetAttribute((const void*)vcomb,
                         cudaFuncAttributeMaxDynamicSharedMemorySize, (int)SMEMVC);

    const int GN = (NN + 127) / 128;   // 782

    zero_denoms_kernel<<<1, 32>>>();
    round_x_kernel<<<12500, 256>>>(x);

    transpose_w<<<dim3(64, 1, 1),  256>>>(wq, WT + 0,      4096, 32, 0,    128, 128);
    transpose_w<<<dim3(64, 1, 5),  256>>>(wk, WT + 16384,  20480, 32, 4096, 128, 128);
    transpose_w<<<dim3(64, 1, 5),  256>>>(wv, WT + 98304,  20480, 32, 4096, 128, 128);
    transpose_w<<<dim3(256, 1, 1), 256>>>(W1, WT + 180224, 32, 512, 0,    128, 512);
    transpose_w<<<dim3(256, 1, 1), 256>>>(W2, WT + 245760, 32, 128, 0,    512, 128);

    // Q = X @ Wq
    tgemm<<<dim3(GN, 1, 1), 256, SMEMSZ>>>(
        (const float*)pX, 128, WT, 128, 4,
        (float*)pQ, 128, 0, nullptr, nullptr, nullptr, nullptr);

    // K GEMM + fused logits + denominators (z = r = 0..4)
    kgemm<<<dim3(GN, 1, 5), 256, SMEMSZ>>>(nbr, WT + 16384);

    // V GEMM x5 + combine + residual + LN1
    vcomb<<<dim3(GN, 1, 1), 256, SMEMVC>>>(nbr, WT + 98304, x, g1, be1);

    // FFN1: relu(Ht @ W1 + b1) -> F (rounded)
    tgemm<<<dim3(GN, 4, 1), 256, SMEMSZ>>>(
        (const float*)pHt, 128, WT + 180224, 128, 4,
        (float*)pF, 512, 1, b1, nullptr, nullptr, nullptr);

    // FFN2 + resid(H exact) + LN2
    tgemm<<<dim3(GN, 1, 1), 256, SMEMSZ>>>(
        (const float*)pF, 512, WT + 245760, 512, 16,
        out, 128, 2, b2, (const float*)pH, g2, be2);
}

// round 9
// speedup vs baseline: 1.4634x; 1.4634x over previous
#include <cuda_runtime.h>
#include <cuda_fp16.h>
#include <cstdint>
#include <math.h>

#define NN 100000

// ---------------- scratch ----------------
__device__ __half g_Xh [(size_t)NN * 128];     // fp16 x
__device__ float  g_Q  [(size_t)NN * 128];
__device__ float  g_K  [(size_t)5 * NN * 128];
__device__ float  g_V  [(size_t)5 * NN * 128];
__device__ float  g_E  [(size_t)NN * 20];
__device__ float  g_H  [(size_t)NN * 128];     // exact H (residual for FFN2)
__device__ __half g_Hth[(size_t)NN * 128];     // fp16 H
__device__ __half g_Fh [(size_t)NN * 512];     // fp16 FFN intermediate
__device__ __half g_WTh[311296];               // transposed fp16 weights [c][k]
__device__ float  g_denom[20];

__device__ __forceinline__ uint32_t smem_u32(const void* p) {
    uint32_t a;
    asm("{ .reg .u64 t; cvta.to.shared.u64 t, %1; cvt.u32.u64 %0, t; }" : "=r"(a) : "l"(p));
    return a;
}
__device__ __forceinline__ void cpa16(uint32_t dst, const void* src) {
    asm volatile("cp.async.ca.shared.global [%0], [%1], 16;" :: "r"(dst), "l"(src));
}

__global__ void zero_denoms_kernel() {
    if (threadIdx.x < 20) g_denom[threadIdx.x] = 0.0f;
}

// x (f32) -> g_Xh (fp16)
__global__ void conv_x_kernel(const float* __restrict__ x) {
    size_t i = ((size_t)blockIdx.x * 256 + threadIdx.x) * 4;
    if (i >= (size_t)NN * 128) return;
    float4 v = *(const float4*)(x + i);
    __half2 h0 = __floats2half2_rn(v.x, v.y);
    __half2 h1 = __floats2half2_rn(v.z, v.w);
    *(__half2*)(g_Xh + i)     = h0;
    *(__half2*)(g_Xh + i + 2) = h1;
}

// out[z][c][k] = half(in[z*inBz + (c>>5)*HS + k*KS + (c&31)])
__global__ void transpose_w(const float* __restrict__ in, __half* __restrict__ out,
                            int HS, int KS, int inBz, int Kb, int Ctot) {
    int z = blockIdx.z;
    int idx = blockIdx.x * 256 + threadIdx.x;
    if (idx >= Ctot * Kb) return;
    int c = idx / Kb, k = idx - c * Kb;
    out[(size_t)z * Ctot * Kb + idx] =
        __float2half_rn(in[(size_t)z * inBz + (size_t)(c >> 5) * HS + (size_t)k * KS + (c & 31)]);
}

#define LDM_X4(r0,r1,r2,r3,addr) \
    asm volatile("ldmatrix.sync.aligned.m8n8.x4.shared.b16 {%0,%1,%2,%3}, [%4];" \
                 : "=r"(r0), "=r"(r1), "=r"(r2), "=r"(r3) : "r"(addr))
#define MMA_F16(dd,aa,bb) \
    asm volatile("mma.sync.aligned.m16n8k16.row.col.f32.f16.f16.f32 " \
                 "{%0,%1,%2,%3}, {%4,%5,%6,%7}, {%8,%9}, {%0,%1,%2,%3};" \
                 : "+f"((dd)[0]), "+f"((dd)[1]), "+f"((dd)[2]), "+f"((dd)[3]) \
                 : "r"((aa)[0]), "r"((aa)[1]), "r"((aa)[2]), "r"((aa)[3]), \
                   "r"((bb)[0]), "r"((bb)[1]))

// ---------------- fp16 mma GEMM, 128x128 CTA tile, k64 smem chunks ----------
// C[gr, cg] = sum_k A[rowmap(gr), k] * BT[cg, k]   (all GEMM inputs fp16)
// epi: 0 plain fp32 store, 1 bias+relu -> fp16 store, 2 bias+resid+LayerNorm fp32
__global__ __launch_bounds__(256, 2)
void tgemm(const __half* __restrict__ A, int Astride,
           const int* __restrict__ nbr,
           const __half* __restrict__ BT, int Kb, size_t BzStride,
           int kchunks,
           float* __restrict__ C, __half* __restrict__ Ch, int Cstride, size_t CzStride,
           int epi,
           const float* __restrict__ bias,
           const float* __restrict__ resid,
           const float* __restrict__ gamma,
           const float* __restrict__ beta)
{
    extern __shared__ uint32_t sm[];
    char* smc = (char*)sm;
    const uint32_t sbase = smem_u32(smc);
    __shared__ int rowg[128];

    const int tid  = threadIdx.x;
    const int wid  = tid >> 5;
    const int lane = tid & 31;
    const int z    = blockIdx.z;
    const int cg0  = blockIdx.y * 128;
    const int m0   = blockIdx.x * 128;
    const int m0w  = (wid >> 1) * 32;
    const int n0w  = (wid & 1) * 64;
    const __half* Bz = BT + (size_t)z * BzStride;
    float* Cp = (C != nullptr) ? C + (size_t)z * CzStride : nullptr;

    if (tid < 128) {
        int gr  = m0 + tid;
        int idx = (gr < NN) ? gr : (NN - 1);
        if (nbr != nullptr && z > 0 && gr < NN) idx = nbr[gr * 4 + (z - 1)];
        rowg[tid] = idx;
    }
    __syncthreads();

    const int srow = tid >> 3, schk = tid & 7;
    const int lrow = lane & 7;
    const int a_hi = (lane >> 3) >> 1, a_roff = ((lane >> 3) & 1) * 8;
    const int b_hi = (lane >> 3) & 1,  b_coff = (lane >> 4) * 8;

    float d[2][8][4];
#pragma unroll
    for (int i = 0; i < 2; i++)
#pragma unroll
        for (int j = 0; j < 8; j++)
#pragma unroll
            for (int q = 0; q < 4; q++) d[i][j][q] = 0.0f;

    // stage one 128x64-half tile pair (16 KB each) into buffer bsel
    auto stage = [&](int bsel, int kc) {
        const int kg0 = kc * 64;                      // halves
        uint32_t abase = sbase + (uint32_t)bsel * 16384u;
        uint32_t bbase = sbase + 32768u + (uint32_t)bsel * 16384u;
#pragma unroll
        for (int p = 0; p < 4; ++p) {
            int row = srow + p * 32;
            uint32_t off = (uint32_t)row * 128u + (uint32_t)((schk ^ (row & 7)) << 4);
            cpa16(abase + off, A + (size_t)rowg[row] * Astride + kg0 + schk * 8);
            cpa16(bbase + off, Bz + (size_t)(cg0 + row) * Kb + kg0 + schk * 8);
        }
        asm volatile("cp.async.commit_group;" ::: "memory");
    };

    stage(0, 0);
    for (int kc = 0; kc < kchunks; ++kc) {
        const int bsel = kc & 1;
        if (kc + 1 < kchunks) { stage(bsel ^ 1, kc + 1);
            asm volatile("cp.async.wait_group 1;" ::: "memory");
        } else { asm volatile("cp.async.wait_group 0;" ::: "memory"); }
        __syncthreads();
        const uint32_t abase = sbase + (uint32_t)bsel * 16384u;
        const uint32_t bbase = sbase + 32768u + (uint32_t)bsel * 16384u;
#pragma unroll
        for (int ks = 0; ks < 4; ++ks) {              // 4 x k16 = 64 k per chunk
            uint32_t a[2][4], b[8][2];
#pragma unroll
            for (int mf = 0; mf < 2; ++mf) {
                int r = m0w + mf * 16 + lrow + a_roff;
                uint32_t addr = abase + (uint32_t)r * 128u
                              + (uint32_t)(((2 * ks + a_hi) ^ lrow) << 4);
                LDM_X4(a[mf][0], a[mf][1], a[mf][2], a[mf][3], addr);
            }
#pragma unroll
            for (int pr = 0; pr < 4; ++pr) {
                int c = n0w + pr * 16 + lrow + b_coff;
                uint32_t addr = bbase + (uint32_t)c * 128u
                              + (uint32_t)(((2 * ks + b_hi) ^ (c & 7)) << 4);
                LDM_X4(b[2*pr][0], b[2*pr][1], b[2*pr+1][0], b[2*pr+1][1], addr);
            }
#pragma unroll
            for (int mf = 0; mf < 2; ++mf)
#pragma unroll
                for (int nf = 0; nf < 8; ++nf) MMA_F16(d[mf][nf], a[mf], b[nf]);
        }
        __syncthreads();
    }

    // stage accumulators into padded smem [128][132]
    float* sC = (float*)sm;
    const int g4 = lane >> 2, t4 = lane & 3;
#pragma unroll
    for (int mf = 0; mf < 2; ++mf)
#pragma unroll
        for (int nf = 0; nf < 8; ++nf) {
            int row = m0w + mf * 16 + g4;
            int col = n0w + nf * 8 + t4 * 2;
            *(float2*)(sC + row * 132 + col)       = make_float2(d[mf][nf][0], d[mf][nf][1]);
            *(float2*)(sC + (row + 8) * 132 + col) = make_float2(d[mf][nf][2], d[mf][nf][3]);
        }
    __syncthreads();

    if (epi == 2) {
        for (int rr = wid; rr < 128; rr += 8) {
            int gr = m0 + rr;
            if (gr >= NN) continue;
            const float* rp = resid + (size_t)gr * 128;
            float v0 = sC[rr * 132 + lane]      + bias[lane]      + rp[lane];
            float v1 = sC[rr * 132 + 32 + lane] + bias[32 + lane] + rp[32 + lane];
            float v2 = sC[rr * 132 + 64 + lane] + bias[64 + lane] + rp[64 + lane];
            float v3 = sC[rr * 132 + 96 + lane] + bias[96 + lane] + rp[96 + lane];
            float s1 = v0 + v1 + v2 + v3;
            float s2 = v0 * v0 + v1 * v1 + v2 * v2 + v3 * v3;
#pragma unroll
            for (int o = 16; o > 0; o >>= 1) {
                s1 += __shfl_xor_sync(0xffffffffu, s1, o);
                s2 += __shfl_xor_sync(0xffffffffu, s2, o);
            }
            float mu  = s1 * (1.0f / 128.0f);
            float var = s2 * (1.0f / 128.0f) - mu * mu;
            float rs  = rsqrtf(var + 1e-5f);
            float* dst = Cp + (size_t)gr * 128;
            dst[lane]      = (v0 - mu) * rs * gamma[lane]      + beta[lane];
            dst[lane + 32] = (v1 - mu) * rs * gamma[lane + 32] + beta[lane + 32];
            dst[lane + 64] = (v2 - mu) * rs * gamma[lane + 64] + beta[lane + 64];
            dst[lane + 96] = (v3 - mu) * rs * gamma[lane + 96] + beta[lane + 96];
        }
    } else if (epi == 1) {
        // bias + relu -> fp16 store (16 halves per thread, 32B)
#pragma unroll
        for (int p = 0; p < 4; ++p) {
            int i   = tid + p * 256;
            int row = i >> 3;
            int q   = (i & 7) << 4;
            int gr  = m0 + row;
            if (gr >= NN) continue;
            __half hb[16];
#pragma unroll
            for (int h = 0; h < 4; ++h) {
                int c = q + h * 4;
                float4 v = *(const float4*)(sC + row * 132 + c);
                int cg = cg0 + c;
                hb[h*4+0] = __float2half_rn(fmaxf(v.x + bias[cg + 0], 0.f));
                hb[h*4+1] = __float2half_rn(fmaxf(v.y + bias[cg + 1], 0.f));
                hb[h*4+2] = __float2half_rn(fmaxf(v.z + bias[cg + 2], 0.f));
                hb[h*4+3] = __float2half_rn(fmaxf(v.w + bias[cg + 3], 0.f));
            }
            __half* dst = Ch + (size_t)gr * Cstride + cg0 + q;
            *(uint4*)(dst)     = *(uint4*)(hb);
            *(uint4*)(dst + 8) = *(uint4*)(hb + 8);
        }
    } else {
#pragma unroll
        for (int p = 0; p < 4; ++p) {
            int i   = tid + p * 256;
            int row = i >> 3;
            int q   = (i & 7) << 4;
            int gr  = m0 + row;
            if (gr >= NN) continue;
#pragma unroll
            for (int h = 0; h < 4; ++h) {
                int c  = q + h * 4;
                float4 v = *(const float4*)(sC + row * 132 + c);
                *(float4*)(Cp + (size_t)gr * Cstride + cg0 + c) = v;
            }
        }
    }
}

// ---------------- logits ----------------
__global__ void logits_kernel() {
    __shared__ float sden[20];
    const int tid = threadIdx.x;
    if (tid < 20) sden[tid] = 0.0f;
    __syncthreads();
    const int n    = blockIdx.x * 8 + (tid >> 5);
    const int lane = tid & 31;
    if (n < NN) {
        const float scale = 0.1767766952966369f;
#pragma unroll
        for (int h = 0; h < 4; h++) {
            float q = g_Q[(size_t)n * 128 + h * 32 + lane];
#pragma unroll
            for (int r = 0; r < 5; r++) {
                float s = q * g_K[((size_t)r * NN + n) * 128 + h * 32 + lane];
#pragma unroll
                for (int o = 16; o > 0; o >>= 1) s += __shfl_xor_sync(0xffffffffu, s, o);
                float e = expf(s * scale);
                if (lane == 0) {
                    g_E[(size_t)n * 20 + h * 5 + r] = e;
                    atomicAdd(&sden[h * 5 + r], e);
                }
            }
        }
    }
    __syncthreads();
    if (tid < 20) atomicAdd(&g_denom[tid], sden[tid]);
}

// ---------------- combine + residual + LN1 ----------------
__global__ void combine_ln1_kernel(const float* __restrict__ x,
                                   const float* __restrict__ g1,
                                   const float* __restrict__ be1) {
    __shared__ float sinv[20];
    const int tid = threadIdx.x;
    if (tid < 20) sinv[tid] = 1.0f / g_denom[tid];
    __syncthreads();
    const int n    = blockIdx.x * 8 + (tid >> 5);
    const int lane = tid & 31;
    if (n >= NN) return;
    float t[4];
    float s1 = 0.0f, s2 = 0.0f;
#pragma unroll
    for (int h = 0; h < 4; h++) {
        float z = 0.0f;
#pragma unroll
        for (int r = 0; r < 5; r++) {
            float p = g_E[(size_t)n * 20 + h * 5 + r] * sinv[h * 5 + r];
            z = fmaf(p, g_V[((size_t)r * NN + n) * 128 + h * 32 + lane], z);
        }
        float v = x[(size_t)n * 128 + h * 32 + lane] + z;
        t[h] = v;
        s1 += v;
        s2 = fmaf(v, v, s2);
    }
#pragma unroll
    for (int o = 16; o > 0; o >>= 1) {
        s1 += __shfl_xor_sync(0xffffffffu, s1, o);
        s2 += __shfl_xor_sync(0xffffffffu, s2, o);
    }
    float mu  = s1 * (1.0f / 128.0f);
    float var = s2 * (1.0f / 128.0f) - mu * mu;
    float rs  = rsqrtf(var + 1e-5f);
#pragma unroll
    for (int h = 0; h < 4; h++) {
        int c = h * 32 + lane;
        float hv = (t[h] - mu) * rs * g1[c] + be1[c];
        g_H  [(size_t)n * 128 + c] = hv;
        g_Hth[(size_t)n * 128 + c] = __float2half_rn(hv);
    }
}

// ---------------- launch ----------------
extern "C" void kernel_launch(void* const* d_in, const int* in_sizes, int n_in,
                              void* d_out, int out_size)
{
    const float* x   = (const float*)d_in[0];
    const int*   nbr = (const int*)  d_in[1];
    const float* wq  = (const float*)d_in[2];
    const float* wk  = (const float*)d_in[3];
    const float* wv  = (const float*)d_in[4];
    const float* W1  = (const float*)d_in[5];
    const float* b1  = (const float*)d_in[6];
    const float* W2  = (const float*)d_in[7];
    const float* b2  = (const float*)d_in[8];
    const float* g1  = (const float*)d_in[9];
    const float* be1 = (const float*)d_in[10];
    const float* g2  = (const float*)d_in[11];
    const float* be2 = (const float*)d_in[12];
    float* out = (float*)d_out;

    void *pXh, *pQ, *pK, *pV, *pH, *pHth, *pFh, *pW;
    cudaGetSymbolAddress(&pXh, g_Xh);
    cudaGetSymbolAddress(&pQ,  g_Q);
    cudaGetSymbolAddress(&pK,  g_K);
    cudaGetSymbolAddress(&pV,  g_V);
    cudaGetSymbolAddress(&pH,  g_H);
    cudaGetSymbolAddress(&pHth, g_Hth);
    cudaGetSymbolAddress(&pFh, g_Fh);
    cudaGetSymbolAddress(&pW,  g_WTh);
    __half* WT = (__half*)pW;

    const size_t SMEMSZ = (size_t)128 * 132 * sizeof(float);   // 67584 (>= 64KB mainloop)
    cudaFuncSetAttribute((const void*)tgemm,
                         cudaFuncAttributeMaxDynamicSharedMemorySize, (int)SMEMSZ);

    const int GN = (NN + 127) / 128;   // 782

    zero_denoms_kernel<<<1, 32>>>();
    conv_x_kernel<<<12500, 256>>>(x);

    transpose_w<<<dim3(64, 1, 1),  256>>>(wq, WT + 0,      4096, 32, 0,    128, 128);
    transpose_w<<<dim3(64, 1, 5),  256>>>(wk, WT + 16384,  20480, 32, 4096, 128, 128);
    transpose_w<<<dim3(64, 1, 5),  256>>>(wv, WT + 98304,  20480, 32, 4096, 128, 128);
    transpose_w<<<dim3(256, 1, 1), 256>>>(W1, WT + 180224, 32, 512, 0,    128, 512);
    transpose_w<<<dim3(256, 1, 1), 256>>>(W2, WT + 245760, 32, 128, 0,    512, 128);

    // Q = Xh @ Wq -> g_Q (f32)
    tgemm<<<dim3(GN, 1, 1), 256, SMEMSZ>>>(
        (const __half*)pXh, 128, nullptr, WT, 128, 0, 2,
        (float*)pQ, nullptr, 128, 0, 0, nullptr, nullptr, nullptr, nullptr);

    // K_r -> g_K (f32), gather
    tgemm<<<dim3(GN, 1, 5), 256, SMEMSZ>>>(
        (const __half*)pXh, 128, nbr, WT + 16384, 128, 16384, 2,
        (float*)pK, nullptr, 128, (size_t)NN * 128, 0, nullptr, nullptr, nullptr, nullptr);

    // V_r -> g_V (f32), gather
    tgemm<<<dim3(GN, 1, 5), 256, SMEMSZ>>>(
        (const __half*)pXh, 128, nbr, WT + 98304, 128, 16384, 2,
        (float*)pV, nullptr, 128, (size_t)NN * 128, 0, nullptr, nullptr, nullptr, nullptr);

    logits_kernel<<<NN / 8, 256>>>();
    combine_ln1_kernel<<<NN / 8, 256>>>(x, g1, be1);

    // FFN1: relu(Hth @ W1 + b1) -> g_Fh (fp16)
    tgemm<<<dim3(GN, 4, 1), 256, SMEMSZ>>>(
        (const __half*)pHth, 128, nullptr, WT + 180224, 128, 0, 2,
        nullptr, (__half*)pFh, 512, 0, 1, b1, nullptr, nullptr, nullptr);

    // FFN2 + resid(H exact) + LN2 -> out
    tgemm<<<dim3(GN, 1, 1), 256, SMEMSZ>>>(
        (const __half*)pFh, 512, nullptr, WT + 245760, 512, 0, 8,
        out, nullptr, 128, 0, 2, b2, (const float*)pH, g2, be2);
}

// round 10
// speedup vs baseline: 1.4849x; 1.0147x over previous
#include <cuda_runtime.h>
#include <cuda_fp16.h>
#include <cstdint>
#include <math.h>

#define NN 100000

// ---------------- scratch ----------------
__device__ __half g_Xh [(size_t)NN * 128];     // fp16 x
__device__ __half g_Qh [(size_t)NN * 128];     // fp16 Q
__device__ __half g_Vh [(size_t)5 * NN * 128]; // fp16 V_r
__device__ float  g_E  [(size_t)NN * 20];
__device__ float  g_H  [(size_t)NN * 128];     // exact H (residual for FFN2)
__device__ __half g_Hth[(size_t)NN * 128];     // fp16 H
__device__ __half g_Fh [(size_t)NN * 512];     // fp16 FFN intermediate
__device__ __half g_WTh[311296];               // transposed fp16 weights [c][k]
__device__ float  g_denom[20];

__device__ __forceinline__ uint32_t smem_u32(const void* p) {
    uint32_t a;
    asm("{ .reg .u64 t; cvta.to.shared.u64 t, %1; cvt.u32.u64 %0, t; }" : "=r"(a) : "l"(p));
    return a;
}
__device__ __forceinline__ void cpa16(uint32_t dst, const void* src) {
    asm volatile("cp.async.ca.shared.global [%0], [%1], 16;" :: "r"(dst), "l"(src));
}

__global__ void zero_denoms_kernel() {
    if (threadIdx.x < 20) g_denom[threadIdx.x] = 0.0f;
}

__global__ void conv_x_kernel(const float* __restrict__ x) {
    size_t i = ((size_t)blockIdx.x * 256 + threadIdx.x) * 4;
    if (i >= (size_t)NN * 128) return;
    float4 v = *(const float4*)(x + i);
    *(__half2*)(g_Xh + i)     = __floats2half2_rn(v.x, v.y);
    *(__half2*)(g_Xh + i + 2) = __floats2half2_rn(v.z, v.w);
}

__global__ void transpose_w(const float* __restrict__ in, __half* __restrict__ out,
                            int HS, int KS, int inBz, int Kb, int Ctot) {
    int z = blockIdx.z;
    int idx = blockIdx.x * 256 + threadIdx.x;
    if (idx >= Ctot * Kb) return;
    int c = idx / Kb, k = idx - c * Kb;
    out[(size_t)z * Ctot * Kb + idx] =
        __float2half_rn(in[(size_t)z * inBz + (size_t)(c >> 5) * HS + (size_t)k * KS + (c & 31)]);
}

#define LDM_X4(r0,r1,r2,r3,addr) \
    asm volatile("ldmatrix.sync.aligned.m8n8.x4.shared.b16 {%0,%1,%2,%3}, [%4];" \
                 : "=r"(r0), "=r"(r1), "=r"(r2), "=r"(r3) : "r"(addr))
#define MMA_F16(dd,aa,bb) \
    asm volatile("mma.sync.aligned.m16n8k16.row.col.f32.f16.f16.f32 " \
                 "{%0,%1,%2,%3}, {%4,%5,%6,%7}, {%8,%9}, {%0,%1,%2,%3};" \
                 : "+f"((dd)[0]), "+f"((dd)[1]), "+f"((dd)[2]), "+f"((dd)[3]) \
                 : "r"((aa)[0]), "r"((aa)[1]), "r"((aa)[2]), "r"((aa)[3]), \
                   "r"((bb)[0]), "r"((bb)[1]))

// ================= shared mainloop body (A fp16, BT fp16 K-contig) ==========
// Computes d[2][8][4] for this CTA tile; tiles staged via cp.async double buffer.
template<typename STAGEF>
__device__ __forceinline__ void mainloop(uint32_t sbase, int kchunks, STAGEF stage,
                                         int m0w, int n0w, int lane,
                                         float d[2][8][4]) {
    const int lrow = lane & 7;
    const int a_hi = (lane >> 3) >> 1, a_roff = ((lane >> 3) & 1) * 8;
    const int b_hi = (lane >> 3) & 1,  b_coff = (lane >> 4) * 8;
    stage(0, 0);
    for (int kc = 0; kc < kchunks; ++kc) {
        const int bsel = kc & 1;
        if (kc + 1 < kchunks) { stage(bsel ^ 1, kc + 1);
            asm volatile("cp.async.wait_group 1;" ::: "memory");
        } else { asm volatile("cp.async.wait_group 0;" ::: "memory"); }
        __syncthreads();
        const uint32_t abase = sbase + (uint32_t)bsel * 16384u;
        const uint32_t bbase = sbase + 32768u + (uint32_t)bsel * 16384u;
#pragma unroll
        for (int ks = 0; ks < 4; ++ks) {
            uint32_t a[2][4], b[8][2];
#pragma unroll
            for (int mf = 0; mf < 2; ++mf) {
                int r = m0w + mf * 16 + lrow + a_roff;
                uint32_t addr = abase + (uint32_t)r * 128u
                              + (uint32_t)(((2 * ks + a_hi) ^ lrow) << 4);
                LDM_X4(a[mf][0], a[mf][1], a[mf][2], a[mf][3], addr);
            }
#pragma unroll
            for (int pr = 0; pr < 4; ++pr) {
                int c = n0w + pr * 16 + lrow + b_coff;
                uint32_t addr = bbase + (uint32_t)c * 128u
                              + (uint32_t)(((2 * ks + b_hi) ^ (c & 7)) << 4);
                LDM_X4(b[2*pr][0], b[2*pr][1], b[2*pr+1][0], b[2*pr+1][1], addr);
            }
#pragma unroll
            for (int mf = 0; mf < 2; ++mf)
#pragma unroll
                for (int nf = 0; nf < 8; ++nf) MMA_F16(d[mf][nf], a[mf], b[nf]);
        }
        __syncthreads();
    }
}

__device__ __forceinline__ void stage_acc(float* sC, int m0w, int n0w, int lane,
                                          float d[2][8][4]) {
    const int g4 = lane >> 2, t4 = lane & 3;
#pragma unroll
    for (int mf = 0; mf < 2; ++mf)
#pragma unroll
        for (int nf = 0; nf < 8; ++nf) {
            int row = m0w + mf * 16 + g4;
            int col = n0w + nf * 8 + t4 * 2;
            *(float2*)(sC + row * 132 + col)       = make_float2(d[mf][nf][0], d[mf][nf][1]);
            *(float2*)(sC + (row + 8) * 132 + col) = make_float2(d[mf][nf][2], d[mf][nf][3]);
        }
}

// ---------------- generic fp16 GEMM ----------------
// epi: 1 bias+relu fp16, 2 bias+resid+LN f32, 3 plain fp16
__global__ __launch_bounds__(256, 2)
void tgemm(const __half* __restrict__ A, int Astride,
           const int* __restrict__ nbr,
           const __half* __restrict__ BT, int Kb, size_t BzStride,
           int kchunks,
           float* __restrict__ C, __half* __restrict__ Ch, int Cstride, size_t CzStride,
           int epi,
           const float* __restrict__ bias,
           const float* __restrict__ resid,
           const float* __restrict__ gamma,
           const float* __restrict__ beta)
{
    extern __shared__ uint32_t sm[];
    char* smc = (char*)sm;
    const uint32_t sbase = smem_u32(smc);
    __shared__ int rowg[128];

    const int tid  = threadIdx.x;
    const int wid  = tid >> 5;
    const int lane = tid & 31;
    const int z    = blockIdx.z;
    const int cg0  = blockIdx.y * 128;
    const int m0   = blockIdx.x * 128;
    const int m0w  = (wid >> 1) * 32;
    const int n0w  = (wid & 1) * 64;
    const __half* Bz = BT + (size_t)z * BzStride;

    if (tid < 128) {
        int gr  = m0 + tid;
        int idx = (gr < NN) ? gr : (NN - 1);
        if (nbr != nullptr && z > 0 && gr < NN) idx = nbr[gr * 4 + (z - 1)];
        rowg[tid] = idx;
    }
    __syncthreads();

    const int srow = tid >> 3, schk = tid & 7;
    float d[2][8][4];
#pragma unroll
    for (int i = 0; i < 2; i++)
#pragma unroll
        for (int j = 0; j < 8; j++)
#pragma unroll
            for (int q = 0; q < 4; q++) d[i][j][q] = 0.0f;

    auto stage = [&](int bsel, int kc) {
        const int kg0 = kc * 64;
        uint32_t abase = sbase + (uint32_t)bsel * 16384u;
        uint32_t bbase = sbase + 32768u + (uint32_t)bsel * 16384u;
#pragma unroll
        for (int p = 0; p < 4; ++p) {
            int row = srow + p * 32;
            uint32_t off = (uint32_t)row * 128u + (uint32_t)((schk ^ (row & 7)) << 4);
            cpa16(abase + off, A + (size_t)rowg[row] * Astride + kg0 + schk * 8);
            cpa16(bbase + off, Bz + (size_t)(cg0 + row) * Kb + kg0 + schk * 8);
        }
        asm volatile("cp.async.commit_group;" ::: "memory");
    };

    mainloop(sbase, kchunks, stage, m0w, n0w, lane, d);

    float* sC = (float*)sm;
    stage_acc(sC, m0w, n0w, lane, d);
    __syncthreads();

    if (epi == 2) {
        float* Cp = C + (size_t)z * CzStride;
        for (int rr = wid; rr < 128; rr += 8) {
            int gr = m0 + rr;
            if (gr >= NN) continue;
            const float* rp = resid + (size_t)gr * 128;
            float v0 = sC[rr * 132 + lane]      + bias[lane]      + rp[lane];
            float v1 = sC[rr * 132 + 32 + lane] + bias[32 + lane] + rp[32 + lane];
            float v2 = sC[rr * 132 + 64 + lane] + bias[64 + lane] + rp[64 + lane];
            float v3 = sC[rr * 132 + 96 + lane] + bias[96 + lane] + rp[96 + lane];
            float s1 = v0 + v1 + v2 + v3;
            float s2 = v0 * v0 + v1 * v1 + v2 * v2 + v3 * v3;
#pragma unroll
            for (int o = 16; o > 0; o >>= 1) {
                s1 += __shfl_xor_sync(0xffffffffu, s1, o);
                s2 += __shfl_xor_sync(0xffffffffu, s2, o);
            }
            float mu  = s1 * (1.0f / 128.0f);
            float var = s2 * (1.0f / 128.0f) - mu * mu;
            float rs  = rsqrtf(var + 1e-5f);
            float* dst = Cp + (size_t)gr * 128;
            dst[lane]      = (v0 - mu) * rs * gamma[lane]      + beta[lane];
            dst[lane + 32] = (v1 - mu) * rs * gamma[lane + 32] + beta[lane + 32];
            dst[lane + 64] = (v2 - mu) * rs * gamma[lane + 64] + beta[lane + 64];
            dst[lane + 96] = (v3 - mu) * rs * gamma[lane + 96] + beta[lane + 96];
        }
    } else {
        __half* Cph = Ch + (size_t)z * CzStride;
#pragma unroll
        for (int p = 0; p < 4; ++p) {
            int i   = tid + p * 256;
            int row = i >> 3;
            int q   = (i & 7) << 4;
            int gr  = m0 + row;
            if (gr >= NN) continue;
            __half hb[16];
#pragma unroll
            for (int h = 0; h < 4; ++h) {
                int c = q + h * 4;
                float4 v = *(const float4*)(sC + row * 132 + c);
                if (epi == 1) {
                    int cg = cg0 + c;
                    v.x = fmaxf(v.x + bias[cg + 0], 0.f);
                    v.y = fmaxf(v.y + bias[cg + 1], 0.f);
                    v.z = fmaxf(v.z + bias[cg + 2], 0.f);
                    v.w = fmaxf(v.w + bias[cg + 3], 0.f);
                }
                hb[h*4+0] = __float2half_rn(v.x);
                hb[h*4+1] = __float2half_rn(v.y);
                hb[h*4+2] = __float2half_rn(v.z);
                hb[h*4+3] = __float2half_rn(v.w);
            }
            __half* dst = Cph + (size_t)gr * Cstride + cg0 + q;
            *(uint4*)(dst)     = *(uint4*)(hb);
            *(uint4*)(dst + 8) = *(uint4*)(hb + 8);
        }
    }
}

// ---------------- K GEMM + fused logits (z = r), no K scratch ----------------
__global__ __launch_bounds__(256, 2)
void kgemm(const int* __restrict__ nbr, const __half* __restrict__ BT)
{
    extern __shared__ uint32_t sm[];
    char* smc = (char*)sm;
    const uint32_t sbase = smem_u32(smc);
    __shared__ int rowg[128];
    __shared__ float sden[20];

    const int tid  = threadIdx.x;
    const int wid  = tid >> 5;
    const int lane = tid & 31;
    const int z    = blockIdx.z;
    const int m0   = blockIdx.x * 128;
    const int m0w  = (wid >> 1) * 32;
    const int n0w  = (wid & 1) * 64;

    if (tid < 128) {
        int gr  = m0 + tid;
        int idx = (gr < NN) ? gr : (NN - 1);
        if (z > 0 && gr < NN) idx = nbr[gr * 4 + (z - 1)];
        rowg[tid] = idx;
    }
    if (tid < 20) sden[tid] = 0.0f;
    __syncthreads();

    const __half* Bz = BT + (size_t)z * 16384;
    const int srow = tid >> 3, schk = tid & 7;

    float d[2][8][4];
#pragma unroll
    for (int i = 0; i < 2; i++)
#pragma unroll
        for (int j = 0; j < 8; j++)
#pragma unroll
            for (int q = 0; q < 4; q++) d[i][j][q] = 0.0f;

    auto stage = [&](int bsel, int kc) {
        const int kg0 = kc * 64;
        uint32_t abase = sbase + (uint32_t)bsel * 16384u;
        uint32_t bbase = sbase + 32768u + (uint32_t)bsel * 16384u;
#pragma unroll
        for (int p = 0; p < 4; ++p) {
            int row = srow + p * 32;
            uint32_t off = (uint32_t)row * 128u + (uint32_t)((schk ^ (row & 7)) << 4);
            cpa16(abase + off, g_Xh + (size_t)rowg[row] * 128 + kg0 + schk * 8);
            cpa16(bbase + off, Bz + (size_t)row * 128 + kg0 + schk * 8);
        }
        asm volatile("cp.async.commit_group;" ::: "memory");
    };

    mainloop(sbase, 2, stage, m0w, n0w, lane, d);

    float* sC = (float*)sm;
    stage_acc(sC, m0w, n0w, lane, d);
    __syncthreads();

    const float scale = 0.1767766952966369f;   // 1/sqrt(32)
    float esum[4] = {0.f, 0.f, 0.f, 0.f};
    for (int rr = wid; rr < 128; rr += 8) {
        int gr = m0 + rr;
        if (gr >= NN) continue;
        const __half* qp = g_Qh + (size_t)gr * 128;
#pragma unroll
        for (int h = 0; h < 4; ++h) {
            float s = sC[rr * 132 + h * 32 + lane] * __half2float(qp[h * 32 + lane]);
#pragma unroll
            for (int o = 16; o > 0; o >>= 1) s += __shfl_xor_sync(0xffffffffu, s, o);
            if (lane == 0) {
                float e = expf(s * scale);
                g_E[(size_t)gr * 20 + h * 5 + z] = e;
                esum[h] += e;
            }
        }
    }
    if (lane == 0) {
#pragma unroll
        for (int h = 0; h < 4; ++h) atomicAdd(&sden[h * 5 + z], esum[h]);
    }
    __syncthreads();
    if (tid < 20 && sden[tid] != 0.0f) atomicAdd(&g_denom[tid], sden[tid]);
}

// ---------------- combine + residual + LN1 (reads fp16 V) ----------------
__global__ void combine_ln1_kernel(const float* __restrict__ x,
                                   const float* __restrict__ g1,
                                   const float* __restrict__ be1) {
    __shared__ float sinv[20];
    const int tid = threadIdx.x;
    if (tid < 20) sinv[tid] = 1.0f / g_denom[tid];
    __syncthreads();
    const int n    = blockIdx.x * 8 + (tid >> 5);
    const int lane = tid & 31;
    if (n >= NN) return;
    float t[4];
    float s1 = 0.0f, s2 = 0.0f;
#pragma unroll
    for (int h = 0; h < 4; h++) {
        float z = 0.0f;
#pragma unroll
        for (int r = 0; r < 5; r++) {
            float p = g_E[(size_t)n * 20 + h * 5 + r] * sinv[h * 5 + r];
            z = fmaf(p, __half2float(g_Vh[((size_t)r * NN + n) * 128 + h * 32 + lane]), z);
        }
        float v = x[(size_t)n * 128 + h * 32 + lane] + z;
        t[h] = v;
        s1 += v;
        s2 = fmaf(v, v, s2);
    }
#pragma unroll
    for (int o = 16; o > 0; o >>= 1) {
        s1 += __shfl_xor_sync(0xffffffffu, s1, o);
        s2 += __shfl_xor_sync(0xffffffffu, s2, o);
    }
    float mu  = s1 * (1.0f / 128.0f);
    float var = s2 * (1.0f / 128.0f) - mu * mu;
    float rs  = rsqrtf(var + 1e-5f);
#pragma unroll
    for (int h = 0; h < 4; h++) {
        int c = h * 32 + lane;
        float hv = (t[h] - mu) * rs * g1[c] + be1[c];
        g_H  [(size_t)n * 128 + c] = hv;
        g_Hth[(size_t)n * 128 + c] = __float2half_rn(hv);
    }
}

// ---------------- launch ----------------
extern "C" void kernel_launch(void* const* d_in, const int* in_sizes, int n_in,
                              void* d_out, int out_size)
{
    const float* x   = (const float*)d_in[0];
    const int*   nbr = (const int*)  d_in[1];
    const float* wq  = (const float*)d_in[2];
    const float* wk  = (const float*)d_in[3];
    const float* wv  = (const float*)d_in[4];
    const float* W1  = (const float*)d_in[5];
    const float* b1  = (const float*)d_in[6];
    const float* W2  = (const float*)d_in[7];
    const float* b2  = (const float*)d_in[8];
    const float* g1  = (const float*)d_in[9];
    const float* be1 = (const float*)d_in[10];
    const float* g2  = (const float*)d_in[11];
    const float* be2 = (const float*)d_in[12];
    float* out = (float*)d_out;

    void *pXh, *pQh, *pVh, *pH, *pHth, *pFh, *pW;
    cudaGetSymbolAddress(&pXh, g_Xh);
    cudaGetSymbolAddress(&pQh, g_Qh);
    cudaGetSymbolAddress(&pVh, g_Vh);
    cudaGetSymbolAddress(&pH,  g_H);
    cudaGetSymbolAddress(&pHth, g_Hth);
    cudaGetSymbolAddress(&pFh, g_Fh);
    cudaGetSymbolAddress(&pW,  g_WTh);
    __half* WT = (__half*)pW;

    const size_t SMEMSZ = (size_t)128 * 132 * sizeof(float);   // 67584
    cudaFuncSetAttribute((const void*)tgemm,
                         cudaFuncAttributeMaxDynamicSharedMemorySize, (int)SMEMSZ);
    cudaFuncSetAttribute((const void*)kgemm,
                         cudaFuncAttributeMaxDynamicSharedMemorySize, (int)SMEMSZ);

    const int GN = (NN + 127) / 128;   // 782

    zero_denoms_kernel<<<1, 32>>>();
    conv_x_kernel<<<12500, 256>>>(x);

    transpose_w<<<dim3(64, 1, 1),  256>>>(wq, WT + 0,      4096, 32, 0,    128, 128);
    transpose_w<<<dim3(64, 1, 5),  256>>>(wk, WT + 16384,  20480, 32, 4096, 128, 128);
    transpose_w<<<dim3(64, 1, 5),  256>>>(wv, WT + 98304,  20480, 32, 4096, 128, 128);
    transpose_w<<<dim3(256, 1, 1), 256>>>(W1, WT + 180224, 32, 512, 0,    128, 512);
    transpose_w<<<dim3(256, 1, 1), 256>>>(W2, WT + 245760, 32, 128, 0,    512, 128);

    // Q = Xh @ Wq -> g_Qh (fp16)
    tgemm<<<dim3(GN, 1, 1), 256, SMEMSZ>>>(
        (const __half*)pXh, 128, nullptr, WT, 128, 0, 2,
        nullptr, (__half*)pQh, 128, 0, 3, nullptr, nullptr, nullptr, nullptr);

    // K GEMM + fused logits + denominators (z = r = 0..4); no K scratch
    kgemm<<<dim3(GN, 1, 5), 256, SMEMSZ>>>(nbr, WT + 16384);

    // V_r -> g_Vh (fp16), gather
    tgemm<<<dim3(GN, 1, 5), 256, SMEMSZ>>>(
        (const __half*)pXh, 128, nbr, WT + 98304, 128, 16384, 2,
        nullptr, (__half*)pVh, 128, (size_t)NN * 128, 3, nullptr, nullptr, nullptr, nullptr);

    combine_ln1_kernel<<<NN / 8, 256>>>(x, g1, be1);

    // FFN1: relu(Hth @ W1 + b1) -> g_Fh (fp16)
    tgemm<<<dim3(GN, 4, 1), 256, SMEMSZ>>>(
        (const __half*)pHth, 128, nullptr, WT + 180224, 128, 0, 2,
        nullptr, (__half*)pFh, 512, 0, 1, b1, nullptr, nullptr, nullptr);

    // FFN2 + resid(H exact) + LN2 -> out
    tgemm<<<dim3(GN, 1, 1), 256, SMEMSZ>>>(
        (const __half*)pFh, 512, nullptr, WT + 245760, 512, 0, 8,
        out, nullptr, 128, 0, 2, b2, (const float*)pH, g2, be2);
}